// round 3
// baseline (speedup 1.0000x reference)
#include <cuda_runtime.h>

// ---------------------------------------------------------------------------
// HiLo attention block, B=1, H=W=96, DIM=128, WS=2
// low path: 4 heads, full-res queries (9216) attend to pooled KV (2304)
// high path: 4 heads, 2x2 windowed attention on high-frequency residual
// ---------------------------------------------------------------------------

#define HPIX 96
#define WPIX 96
#define NPIX 9216          // 96*96
#define CDIM 128
#define NS   2304          // 48*48 pooled tokens
#define ATTN_SCALE 0.25f   // 16^-0.5

typedef unsigned long long u64;

// -------------------- scratch (device globals; no allocation) --------------
__device__ float g_low [NS   * 128];   // pooled features
__device__ float g_l2h [NPIX * 32];    // pixel-shuffled low
__device__ float g_high[NPIX * 128];   // high-frequency residual
__device__ float g_lq  [NPIX * 64];    // low-path queries  [n][h*16+d]
__device__ float g_lkv [NS   * 128];   // low-path K|V      [m][kv*64+h*16+d]
__device__ float g_hqkv[NPIX * 192];   // high-path QKV     [p][s*64+h*16+d]
__device__ float g_lxp [NPIX * 64];    // low attention out (pre-proj)
__device__ float g_ho  [NPIX * 64];    // high attention out (pre-proj)

// -------------------- scalar helpers ---------------------------------------
__device__ __forceinline__ float dot4(float4 a, float4 b) {
    return a.x*b.x + a.y*b.y + a.z*b.z + a.w*b.w;
}
__device__ __forceinline__ void fma4(float4& a, float s, float4 v) {
    a.x = fmaf(s, v.x, a.x); a.y = fmaf(s, v.y, a.y);
    a.z = fmaf(s, v.z, a.z); a.w = fmaf(s, v.w, a.w);
}
__device__ __forceinline__ void scale4(float4& a, float s) {
    a.x *= s; a.y *= s; a.z *= s; a.w *= s;
}

// -------------------- packed f32x2 helpers (sm_100+ PTX) --------------------
__device__ __forceinline__ u64 pack2(float lo, float hi) {
    u64 r; asm("mov.b64 %0, {%1, %2};" : "=l"(r) : "f"(lo), "f"(hi)); return r;
}
__device__ __forceinline__ void unpack2(u64 v, float& lo, float& hi) {
    asm("mov.b64 {%0, %1}, %2;" : "=f"(lo), "=f"(hi) : "l"(v));
}
__device__ __forceinline__ u64 fma2(u64 a, u64 b, u64 c) {
    u64 d; asm("fma.rn.f32x2 %0, %1, %2, %3;" : "=l"(d) : "l"(a), "l"(b), "l"(c)); return d;
}
__device__ __forceinline__ u64 mul2(u64 a, u64 b) {
    u64 d; asm("mul.rn.f32x2 %0, %1, %2;" : "=l"(d) : "l"(a), "l"(b)); return d;
}

// -------------------- avg pool 2x2 -----------------------------------------
__global__ void pool_kernel(const float* __restrict__ x, float* __restrict__ low) {
    int m = blockIdx.x;          // pooled token 0..2303
    int c = threadIdx.x;         // channel 0..127
    int hs = m / 48, ws = m % 48;
    int p00 = (2*hs) * 96 + 2*ws;
    float v = x[p00*128 + c] + x[(p00+1)*128 + c]
            + x[(p00+96)*128 + c] + x[(p00+97)*128 + c];
    low[m*128 + c] = 0.25f * v;
}

// -------------------- pixel shuffle gather ----------------------------------
__global__ void l2h_kernel(const float* __restrict__ low, float* __restrict__ l2h) {
    int idx = blockIdx.x * blockDim.x + threadIdx.x;
    if (idx >= NPIX * 32) return;
    int p = idx >> 5, i = idx & 31;
    int h = p / 96, w = p % 96;
    l2h[idx] = low[((h >> 1) * 48 + (w >> 1)) * 128 + i*4 + (h & 1)*2 + (w & 1)];
}

// -------------------- generic tiled GEMM: C = A @ W^T (+bias)(-sub) --------
// A: M x K row-major;  W: N x K row-major;  C written at [m*ldc + coff + n]
template<int BM, int BN, int BK>
__global__ __launch_bounds__(256)
void gemm_kernel(const float* __restrict__ A, const float* __restrict__ Wm,
                 const float* __restrict__ bias, const float* __restrict__ sub,
                 float* __restrict__ Cp, int M, int N, int K, int ldc, int coff) {
    constexpr int TM = 4, TN = 4;
    constexpr int THREADS = (BM/TM) * (BN/TN);   // 256
    __shared__ float As[BK][BM + 4];
    __shared__ float Ws[BK][BN + 4];
    int tid  = threadIdx.x;
    int tcol = tid % (BN/TN);    // 0..15
    int trow = tid / (BN/TN);    // 0..15
    int m0 = blockIdx.x * BM;
    int n0 = blockIdx.y * BN;
    float acc[TM][TN] = {};

    for (int k0 = 0; k0 < K; k0 += BK) {
        for (int i = tid; i < BM * BK / 4; i += THREADS) {
            int m  = i / (BK/4);
            int kq = i % (BK/4);
            float4 v = *(const float4*)&A[(m0+m)*K + k0 + kq*4];
            As[kq*4+0][m] = v.x; As[kq*4+1][m] = v.y;
            As[kq*4+2][m] = v.z; As[kq*4+3][m] = v.w;
        }
        for (int i = tid; i < BN * BK / 4; i += THREADS) {
            int n  = i / (BK/4);
            int kq = i % (BK/4);
            float4 v = *(const float4*)&Wm[(n0+n)*K + k0 + kq*4];
            Ws[kq*4+0][n] = v.x; Ws[kq*4+1][n] = v.y;
            Ws[kq*4+2][n] = v.z; Ws[kq*4+3][n] = v.w;
        }
        __syncthreads();
        #pragma unroll
        for (int k = 0; k < BK; k++) {
            float4 av = *(const float4*)&As[k][trow*4];
            float4 wv = *(const float4*)&Ws[k][tcol*4];
            float a[4] = {av.x, av.y, av.z, av.w};
            float w[4] = {wv.x, wv.y, wv.z, wv.w};
            #pragma unroll
            for (int i = 0; i < TM; i++)
                #pragma unroll
                for (int j = 0; j < TN; j++)
                    acc[i][j] = fmaf(a[i], w[j], acc[i][j]);
        }
        __syncthreads();
    }

    #pragma unroll
    for (int i = 0; i < TM; i++) {
        int m = m0 + trow*4 + i;
        #pragma unroll
        for (int j = 0; j < TN; j++) {
            int n = n0 + tcol*4 + j;
            float c = acc[i][j];
            if (bias) c += bias[n];
            if (sub)  c -= sub[m*ldc + coff + n];
            Cp[m*ldc + coff + n] = c;
        }
    }
}

// -------------------- low-frequency flash attention (packed f32x2) ----------
// grid (144, 4): 64 queries per block (1 thread each), head = blockIdx.y
__global__ __launch_bounds__(64)
void low_attn_kernel(const float* __restrict__ lq, const float* __restrict__ lkv,
                     float* __restrict__ lxp) {
    constexpr int TK = 64;
    int head = blockIdx.y;
    int tid  = threadIdx.x;
    int q    = blockIdx.x * 64 + tid;

    // load + pre-scale query as 8 packed f32x2
    u64 q2[8];
    {
        const u64* qp = (const u64*)&lq[q*64 + head*16];
        u64 s2 = pack2(ATTN_SCALE, ATTN_SCALE);
        #pragma unroll
        for (int i = 0; i < 8; i++) q2[i] = mul2(qp[i], s2);
    }

    u64 acc[8];
    #pragma unroll
    for (int i = 0; i < 8; i++) acc[i] = pack2(0.f, 0.f);
    float lsum = 0.f;

    __shared__ __align__(16) u64 Ks[TK * 8];
    __shared__ __align__(16) u64 Vs[TK * 8];

    for (int t = 0; t < NS; t += TK) {
        __syncthreads();
        #pragma unroll
        for (int i = tid; i < TK * 8; i += 64) {
            int row = i >> 3, part = i & 7;   // part: 4 float4 of K then 4 of V
            int col = (part < 4) ? (head*16 + part*4) : (64 + head*16 + (part-4)*4);
            float4 v = *(const float4*)&lkv[(t + row)*128 + col];
            u64* dst = (part < 4) ? &Ks[row*8 + part*2] : &Vs[row*8 + (part-4)*2];
            *(float4*)dst = v;
        }
        __syncthreads();
        #pragma unroll 2
        for (int j = 0; j < TK; j++) {
            const u64* kr = &Ks[j*8];
            u64 d2 = mul2(q2[0], kr[0]);
            #pragma unroll
            for (int i = 1; i < 8; i++) d2 = fma2(q2[i], kr[i], d2);
            float lo, hi; unpack2(d2, lo, hi);
            float e = __expf(lo + hi);   // logits ~|0.1|: no max-subtraction needed
            lsum += e;
            u64 e2 = pack2(e, e);
            const u64* vr = &Vs[j*8];
            #pragma unroll
            for (int i = 0; i < 8; i++) acc[i] = fma2(e2, vr[i], acc[i]);
        }
    }
    u64 inv2 = pack2(1.f / lsum, 1.f / lsum);
    u64* o = (u64*)&lxp[q*64 + head*16];
    #pragma unroll
    for (int i = 0; i < 8; i++) o[i] = mul2(acc[i], inv2);
}

// -------------------- high-frequency 2x2 windowed attention -----------------
// one thread per (window, head, query-pos): 2304*4*4 = 36864 threads
__global__ void high_attn_kernel(const float* __restrict__ hqkv, float* __restrict__ ho) {
    int idx = blockIdx.x * blockDim.x + threadIdx.x;
    if (idx >= NPIX * 4) return;
    int r    = idx & 3;
    int head = (idx >> 2) & 3;
    int g    = idx >> 4;                // window 0..2303
    int hg = g / 48, wg = g % 48;
    int p  = (hg*2 + (r >> 1)) * 96 + wg*2 + (r & 1);

    const float4* qp = (const float4*)&hqkv[p*192 + head*16];
    float4 q0 = qp[0], q1 = qp[1], q2 = qp[2], q3 = qp[3];
    scale4(q0, ATTN_SCALE); scale4(q1, ATTN_SCALE);
    scale4(q2, ATTN_SCALE); scale4(q3, ATTN_SCALE);

    float e[4]; int pid[4]; float lsum = 0.f;
    #pragma unroll
    for (int rr = 0; rr < 4; rr++) {
        int pp = (hg*2 + (rr >> 1)) * 96 + wg*2 + (rr & 1);
        pid[rr] = pp;
        const float4* kp = (const float4*)&hqkv[pp*192 + 64 + head*16];
        float s = (dot4(q0, kp[0]) + dot4(q1, kp[1]))
                + (dot4(q2, kp[2]) + dot4(q3, kp[3]));
        e[rr] = __expf(s);
        lsum += e[rr];
    }
    float4 a0 = {0,0,0,0}, a1 = {0,0,0,0}, a2 = {0,0,0,0}, a3 = {0,0,0,0};
    #pragma unroll
    for (int rr = 0; rr < 4; rr++) {
        const float4* vp = (const float4*)&hqkv[pid[rr]*192 + 128 + head*16];
        fma4(a0, e[rr], vp[0]); fma4(a1, e[rr], vp[1]);
        fma4(a2, e[rr], vp[2]); fma4(a3, e[rr], vp[3]);
    }
    float inv = 1.f / lsum;
    scale4(a0, inv); scale4(a1, inv); scale4(a2, inv); scale4(a3, inv);
    float4* o = (float4*)&ho[p*64 + head*16];
    o[0] = a0; o[1] = a1; o[2] = a2; o[3] = a3;
}

// -------------------- launch -------------------------------------------------
extern "C" void kernel_launch(void* const* d_in, const int* in_sizes, int n_in,
                              void* d_out, int out_size) {
    const float* x         = (const float*)d_in[0];
    const float* restore_w = (const float*)d_in[1];
    const float* restore_b = (const float*)d_in[2];
    const float* l_q_w     = (const float*)d_in[3];
    const float* l_kv_w    = (const float*)d_in[4];
    const float* l_proj_w  = (const float*)d_in[5];
    const float* l_proj_b  = (const float*)d_in[6];
    const float* h_qkv_w   = (const float*)d_in[7];
    const float* h_proj_w  = (const float*)d_in[8];
    const float* h_proj_b  = (const float*)d_in[9];
    float* out = (float*)d_out;

    float *low, *l2h, *high, *lq, *lkv, *hqkv, *lxp, *ho;
    cudaGetSymbolAddress((void**)&low,  g_low);
    cudaGetSymbolAddress((void**)&l2h,  g_l2h);
    cudaGetSymbolAddress((void**)&high, g_high);
    cudaGetSymbolAddress((void**)&lq,   g_lq);
    cudaGetSymbolAddress((void**)&lkv,  g_lkv);
    cudaGetSymbolAddress((void**)&hqkv, g_hqkv);
    cudaGetSymbolAddress((void**)&lxp,  g_lxp);
    cudaGetSymbolAddress((void**)&ho,   g_ho);

    // 1. pooled low features
    pool_kernel<<<NS, 128>>>(x, low);
    // 2. pixel-shuffle gather
    l2h_kernel<<<(NPIX*32 + 255)/256, 256>>>(low, l2h);
    // 3. low-path queries: x @ l_q_w^T           (9216 x 64 x 128)
    gemm_kernel<64,64,32><<<dim3(144,1), 256>>>(x, l_q_w, nullptr, nullptr,
                                                lq, NPIX, 64, 128, 64, 0);
    // 4. low-path KV: low @ l_kv_w^T             (2304 x 128 x 128)
    gemm_kernel<64,64,32><<<dim3(36,2), 256>>>(low, l_kv_w, nullptr, nullptr,
                                               lkv, NS, 128, 128, 128, 0);
    // 5. high residual: l2h @ restore_w^T + b - x (9216 x 128 x 32)
    gemm_kernel<64,64,32><<<dim3(144,2), 256>>>(l2h, restore_w, restore_b, x,
                                                high, NPIX, 128, 32, 128, 0);
    // 6. high QKV: high @ h_qkv_w^T              (9216 x 192 x 128)
    gemm_kernel<64,64,32><<<dim3(144,3), 256>>>(high, h_qkv_w, nullptr, nullptr,
                                                hqkv, NPIX, 192, 128, 192, 0);
    // 7. low attention (dominant cost)
    low_attn_kernel<<<dim3(144,4), 64>>>(lq, lkv, lxp);
    // 8. high windowed attention
    high_attn_kernel<<<(NPIX*4 + 127)/128, 128>>>(hqkv, ho);
    // 9. low projection -> out[:, 0:64]
    gemm_kernel<64,64,32><<<dim3(144,1), 256>>>(lxp, l_proj_w, l_proj_b, nullptr,
                                                out, NPIX, 64, 64, 128, 0);
    // 10. high projection -> out[:, 64:128]
    gemm_kernel<64,64,32><<<dim3(144,1), 256>>>(ho, h_proj_w, h_proj_b, nullptr,
                                                out, NPIX, 64, 64, 128, 64);
}